// round 5
// baseline (speedup 1.0000x reference)
#include <cuda_runtime.h>
#include <math.h>

#define Bb 8
#define Tt 2048
#define Ee 1024
#define Hd 128
#define NROW (Bb * Tt)

// Scratch for Q, K, V (8 MB each) — __device__ globals per allocation rules.
__device__ float g_Q[NROW * Hd];
__device__ float g_K[NROW * Hd];
__device__ float g_V[NROW * Hd];

// ---------------------------------------------------------------------------
// Kernel 1: QKV projection. C[16384,128] = X[16384,1024] @ W[1024,128], x3.
// 128x128x8 tiles, 256 threads, 8x8 microtile (split 4+4), double-buffered smem.
// ---------------------------------------------------------------------------
__global__ __launch_bounds__(256, 2) void qkv_kernel(
    const float* __restrict__ x,
    const float* __restrict__ Wq,
    const float* __restrict__ Wk,
    const float* __restrict__ Wv)
{
    __shared__ float As[2][8][128];  // [buf][k][row]
    __shared__ float Bs[2][8][128];  // [buf][k][col]

    const int which = blockIdx.y;
    const float* __restrict__ W = (which == 0) ? Wq : ((which == 1) ? Wk : Wv);
    float* __restrict__ out = (which == 0) ? g_Q : ((which == 1) ? g_K : g_V);

    const int tid = threadIdx.x;
    const int tx = tid & 15;
    const int ty = tid >> 4;
    const int m0 = blockIdx.x * 128;

    const int arow = tid >> 1;          // 0..127
    const int acol = (tid & 1) * 4;     // 0 or 4
    const int brow = tid >> 5;          // 0..7
    const int bcol = (tid & 31) * 4;    // 0..124

    const float* xg = x + (size_t)(m0 + arow) * Ee + acol;
    const float* wg = W + (size_t)brow * Hd + bcol;

    float acc[8][8];
#pragma unroll
    for (int i = 0; i < 8; ++i)
#pragma unroll
        for (int j = 0; j < 8; ++j) acc[i][j] = 0.0f;

    // preload tile 0
    {
        float4 a = *(const float4*)xg;
        float4 bv = *(const float4*)wg;
        As[0][acol + 0][arow] = a.x;
        As[0][acol + 1][arow] = a.y;
        As[0][acol + 2][arow] = a.z;
        As[0][acol + 3][arow] = a.w;
        *(float4*)&Bs[0][brow][bcol] = bv;
    }
    __syncthreads();

    int buf = 0;
    const int NT = Ee / 8;  // 128 k-tiles
    for (int t = 0; t < NT; ++t) {
        float4 a2, b2;
        if (t < NT - 1) {
            a2 = *(const float4*)(xg + (size_t)(t + 1) * 8);
            b2 = *(const float4*)(wg + (size_t)(t + 1) * 8 * Hd);
        }
#pragma unroll
        for (int k = 0; k < 8; ++k) {
            float4 a0 = *(const float4*)&As[buf][k][ty * 4];
            float4 a1 = *(const float4*)&As[buf][k][64 + ty * 4];
            float4 b0 = *(const float4*)&Bs[buf][k][tx * 4];
            float4 b1 = *(const float4*)&Bs[buf][k][64 + tx * 4];
            float af[8] = {a0.x, a0.y, a0.z, a0.w, a1.x, a1.y, a1.z, a1.w};
            float bf[8] = {b0.x, b0.y, b0.z, b0.w, b1.x, b1.y, b1.z, b1.w};
#pragma unroll
            for (int i = 0; i < 8; ++i)
#pragma unroll
                for (int j = 0; j < 8; ++j)
                    acc[i][j] = fmaf(af[i], bf[j], acc[i][j]);
        }
        if (t < NT - 1) {
            buf ^= 1;
            As[buf][acol + 0][arow] = a2.x;
            As[buf][acol + 1][arow] = a2.y;
            As[buf][acol + 2][arow] = a2.z;
            As[buf][acol + 3][arow] = a2.w;
            *(float4*)&Bs[buf][brow][bcol] = b2;
        }
        __syncthreads();
    }

    // epilogue
#pragma unroll
    for (int ih = 0; ih < 2; ++ih) {
#pragma unroll
        for (int i = 0; i < 4; ++i) {
            int row = m0 + ih * 64 + ty * 4 + i;
            float* op = out + (size_t)row * Hd;
            int ii = ih * 4 + i;
            float4 v0 = make_float4(acc[ii][0], acc[ii][1], acc[ii][2], acc[ii][3]);
            float4 v1 = make_float4(acc[ii][4], acc[ii][5], acc[ii][6], acc[ii][7]);
            *(float4*)&op[tx * 4] = v0;
            *(float4*)&op[64 + tx * 4] = v1;
        }
    }
}

// ---------------------------------------------------------------------------
// Kernel 2: flash attention, causal, fp32, scale = sqrt(2048).
// BQ = BK = 64, 256 threads. Each block processes q-tiles (qa, 31-qa) so all
// 128 blocks do exactly 33 k-tile units -> one balanced wave across SMs.
// ---------------------------------------------------------------------------
#define QS_STRIDE 68
#define PS_STRIDE 68
#define ATTN_SMEM_FLOATS (128 * QS_STRIDE /*Qs*/ + 128 * QS_STRIDE /*Ks*/ + 64 * 128 /*Vs*/ + 64 * PS_STRIDE /*Ps*/)
#define ATTN_SMEM_BYTES (ATTN_SMEM_FLOATS * 4)

__global__ __launch_bounds__(256, 1) void attn_kernel(float* __restrict__ out)
{
    extern __shared__ float sm[];
    float* Qs = sm;                                  // [128][68]  (h-major)
    float* Ks = sm + 128 * QS_STRIDE;                // [128][68]  (h-major)
    float* Vs = sm + 2 * 128 * QS_STRIDE;            // [64][128]  (key-major)
    float* Ps = sm + 2 * 128 * QS_STRIDE + 64 * 128; // [64][68]   (key-major)

    const int tid = threadIdx.x;
    const int tx = tid & 15;
    const int ty = tid >> 4;
    const int b = blockIdx.y;
    const float scale = 45.25483399593904f;  // sqrt(2048)

    for (int half = 0; half < 2; ++half) {
        const int qt = half ? (31 - (int)blockIdx.x) : (int)blockIdx.x;

        __syncthreads();  // protect smem reuse across halves

        // Load Q tile transposed: Qs[h][r]
        {
            const float* Qg = g_Q + (size_t)(b * Tt + qt * 64) * Hd;
            for (int idx = tid; idx < 64 * 128; idx += 256) {
                int r = idx >> 7;
                int c = idx & 127;
                Qs[c * QS_STRIDE + r] = Qg[idx];
            }
        }

        float m_i[4], l_i[4], o[4][8];
#pragma unroll
        for (int i = 0; i < 4; ++i) {
            m_i[i] = -INFINITY;
            l_i[i] = 0.0f;
#pragma unroll
            for (int j = 0; j < 8; ++j) o[i][j] = 0.0f;
        }

        for (int kt = 0; kt <= qt; ++kt) {
            __syncthreads();  // previous PV done; Q tile visible (first iter)

            // Load K tile transposed (Ks[h][key]) and V tile (Vs[key][h])
            const float* Kg = g_K + (size_t)(b * Tt + kt * 64) * Hd;
            const float* Vg = g_V + (size_t)(b * Tt + kt * 64) * Hd;
            for (int idx = tid; idx < 64 * 128; idx += 256) {
                int r = idx >> 7;
                int c = idx & 127;
                Ks[c * QS_STRIDE + r] = Kg[idx];
            }
            for (int idx = tid; idx < 64 * 32; idx += 256) {
                int r = idx >> 5;
                int c4 = (idx & 31) << 2;
                *(float4*)&Vs[r * 128 + c4] = *(const float4*)&Vg[(size_t)r * 128 + c4];
            }
            __syncthreads();

            // S = Q K^T : rows ty*4.., cols tx*4..
            float s[4][4];
#pragma unroll
            for (int i = 0; i < 4; ++i)
#pragma unroll
                for (int j = 0; j < 4; ++j) s[i][j] = 0.0f;

#pragma unroll 8
            for (int kk = 0; kk < 128; ++kk) {
                float4 qa = *(const float4*)&Qs[kk * QS_STRIDE + ty * 4];
                float4 kb = *(const float4*)&Ks[kk * QS_STRIDE + tx * 4];
                float af[4] = {qa.x, qa.y, qa.z, qa.w};
                float bf[4] = {kb.x, kb.y, kb.z, kb.w};
#pragma unroll
                for (int i = 0; i < 4; ++i)
#pragma unroll
                    for (int j = 0; j < 4; ++j)
                        s[i][j] = fmaf(af[i], bf[j], s[i][j]);
            }

            // scale + causal mask (only diagonal tile needs masking)
#pragma unroll
            for (int i = 0; i < 4; ++i)
#pragma unroll
                for (int j = 0; j < 4; ++j) {
                    s[i][j] *= scale;
                    if (kt == qt && (tx * 4 + j) > (ty * 4 + i)) s[i][j] = -INFINITY;
                }

            // online softmax: reductions across the 16 tx lanes of each row group
            float p[4][4];
#pragma unroll
            for (int i = 0; i < 4; ++i) {
                float mt = fmaxf(fmaxf(s[i][0], s[i][1]), fmaxf(s[i][2], s[i][3]));
#pragma unroll
                for (int off = 8; off > 0; off >>= 1)
                    mt = fmaxf(mt, __shfl_xor_sync(0xffffffffu, mt, off));
                float m_new = fmaxf(m_i[i], mt);
                float alpha = __expf(m_i[i] - m_new);
                float ls = 0.0f;
#pragma unroll
                for (int j = 0; j < 4; ++j) {
                    p[i][j] = __expf(s[i][j] - m_new);
                    ls += p[i][j];
                }
#pragma unroll
                for (int off = 8; off > 0; off >>= 1)
                    ls += __shfl_xor_sync(0xffffffffu, ls, off);
                l_i[i] = l_i[i] * alpha + ls;
                m_i[i] = m_new;
#pragma unroll
                for (int jj = 0; jj < 8; ++jj) o[i][jj] *= alpha;
            }

            // stash P transposed: Ps[key][q]
#pragma unroll
            for (int i = 0; i < 4; ++i)
#pragma unroll
                for (int j = 0; j < 4; ++j)
                    Ps[(tx * 4 + j) * PS_STRIDE + ty * 4 + i] = p[i][j];
            __syncthreads();

            // O += P V : rows ty*4.., cols tx*8..
#pragma unroll 8
            for (int kk = 0; kk < 64; ++kk) {
                float4 pa = *(const float4*)&Ps[kk * PS_STRIDE + ty * 4];
                float4 v0 = *(const float4*)&Vs[kk * 128 + tx * 8];
                float4 v1 = *(const float4*)&Vs[kk * 128 + tx * 8 + 4];
                float af[4] = {pa.x, pa.y, pa.z, pa.w};
                float bf[8] = {v0.x, v0.y, v0.z, v0.w, v1.x, v1.y, v1.z, v1.w};
#pragma unroll
                for (int i = 0; i < 4; ++i)
#pragma unroll
                    for (int jj = 0; jj < 8; ++jj)
                        o[i][jj] = fmaf(af[i], bf[jj], o[i][jj]);
            }
        }

        // epilogue: normalize and store
#pragma unroll
        for (int i = 0; i < 4; ++i) {
            float inv = 1.0f / l_i[i];
            int q = qt * 64 + ty * 4 + i;
            float* op = out + (size_t)(b * Tt + q) * Hd + tx * 8;
            float4 r0 = make_float4(o[i][0] * inv, o[i][1] * inv, o[i][2] * inv, o[i][3] * inv);
            float4 r1 = make_float4(o[i][4] * inv, o[i][5] * inv, o[i][6] * inv, o[i][7] * inv);
            *(float4*)&op[0] = r0;
            *(float4*)&op[4] = r1;
        }
    }
}

// ---------------------------------------------------------------------------

extern "C" void kernel_launch(void* const* d_in, const int* in_sizes, int n_in,
                              void* d_out, int out_size)
{
    const float* x  = (const float*)d_in[0];
    const float* Wq = (const float*)d_in[1];
    const float* Wk = (const float*)d_in[2];
    const float* Wv = (const float*)d_in[3];
    float* out = (float*)d_out;

    dim3 g1(NROW / 128, 3);
    qkv_kernel<<<g1, 256>>>(x, Wq, Wk, Wv);

    cudaFuncSetAttribute(attn_kernel, cudaFuncAttributeMaxDynamicSharedMemorySize,
                         ATTN_SMEM_BYTES);
    dim3 g2(16, Bb);  // 16 paired q-tiles x 8 batches
    attn_kernel<<<g2, 256, ATTN_SMEM_BYTES>>>(out);
}